// round 10
// baseline (speedup 1.0000x reference)
#include <cuda_runtime.h>
#include <cuda_fp16.h>
#include <cstdint>

#define HID 256
#define MTILE 128

#define AROWB 528
// ---- smem byte offsets (all 16B aligned) ----
#define OFF_A    0        // 128 * 528 = 67584
#define OFF_B1   67584    // 256 f32
#define OFF_B2   68608    // 256 f32
#define OFF_W3   69632    // [3][256] f32
#define OFF_B3   72704    // 4 f32
#define OFF_W0   72720    // 768 f32
#define OFF_CV   75792    // 256 f32
#define OFF_RGB  76816    // 384 f32
#define OFF_RED  78352    // 128*3*4 f32
#define SMEM_TOT 84496

// B in mma-fragment order:
// index = ((((l*4 + wn)*16 + ks)*32 + lane)*16 + r), r = nt*2 + rh
// value = half2( W[k][n], W[k+1][n] ), n = wn*64 + (r>>1)*8 + lane/4,
//         k = ks*16 + (r&1)*8 + (lane&3)*2
__device__ __align__(16) uint32_t g_bfrag[65536];
__device__ float g_cstyle[16 * HID];

// ---------- helpers ----------
__device__ __forceinline__ uint32_t s2u(const void* p) {
    uint32_t a;
    asm("{ .reg .u64 t; cvta.to.shared.u64 t, %1; cvt.u32.u64 %0, t; }" : "=r"(a) : "l"(p));
    return a;
}
__device__ __forceinline__ void ldsm4(uint32_t* r, uint32_t addr) {
    asm volatile("ldmatrix.sync.aligned.m8n8.x4.shared.b16 {%0,%1,%2,%3}, [%4];"
                 : "=r"(r[0]), "=r"(r[1]), "=r"(r[2]), "=r"(r[3]) : "r"(addr));
}
// fp16-accumulate mma: D/C are 2 packed b32 regs (each = half2)
__device__ __forceinline__ void mma16816h(uint32_t* d, const uint32_t* a, uint32_t b0, uint32_t b1) {
    asm volatile("mma.sync.aligned.m16n8k16.row.col.f16.f16.f16.f16 "
                 "{%0,%1}, {%2,%3,%4,%5}, {%6,%7}, {%0,%1};"
                 : "+r"(d[0]), "+r"(d[1])
                 : "r"(a[0]), "r"(a[1]), "r"(a[2]), "r"(a[3]), "r"(b0), "r"(b1));
}
__device__ __forceinline__ float gelu_f(float x) {
    return 0.5f * x * (1.0f + erff(x * 0.70710678118654752f));
}
__device__ __forceinline__ uint32_t pack_h2(float lo, float hi) {
    __half2 h = __floats2half2_rn(lo, hi);
    return *(uint32_t*)&h;
}
__device__ __forceinline__ float2 unpack_h2(uint32_t v) {
    return __half22float2(*(__half2*)&v);
}

// ---------- merged pre-kernel ----------
// blocks [0, 256): fragment-order weight convert; blocks [256, 256+B): style vector
__global__ void prep_all(const float* __restrict__ W1, const float* __restrict__ W2,
                         const int* __restrict__ sidx, const float* __restrict__ emb,
                         const float* __restrict__ W0, const float* __restrict__ b0) {
    if (blockIdx.x < 256) {
        int idx = blockIdx.x * 256 + threadIdx.x;     // 0..65535
        int r    = idx & 15;
        int lane = (idx >> 4) & 31;
        int ks   = (idx >> 9) & 15;
        int wn   = (idx >> 13) & 3;
        int l    = (idx >> 15) & 1;
        int n = wn * 64 + (r >> 1) * 8 + (lane >> 2);
        int k = ks * 16 + (r & 1) * 8 + (lane & 3) * 2;
        const float* Wm = l ? W2 : W1;
        g_bfrag[idx] = pack_h2(Wm[k * HID + n], Wm[(k + 1) * HID + n]);
    } else {
        int b = blockIdx.x - 256, j = threadIdx.x;
        int s = sidx[b];
        float acc = b0[j];
#pragma unroll 8
        for (int k = 0; k < 64; k++)
            acc = fmaf(emb[s * 64 + k], W0[(3 + k) * HID + j], acc);
        g_cstyle[b * HID + j] = acc;
    }
}

// ---------- main kernel ----------
// One layer: C += A(smem) * B(global fragments). bb[0] must hold ks=0 data on entry.
// On exit, bb[0] holds the first k-step of bpn (if bpn != null).
__device__ __forceinline__ void run_layer(uint32_t sbA, const uint4* bp, const uint4* bpn,
                                          int M0, int arow, int ak16off,
                                          uint32_t C[4][8][2], uint4 bb[2][4]) {
#pragma unroll
    for (int ks = 0; ks < 16; ks++) {
        uint4* cur = bb[ks & 1];
        uint4* nxt = bb[(ks + 1) & 1];
        const uint4* np = (ks < 15) ? bp + (ks + 1) * 128 : bpn;
        if (np) {
            nxt[0] = __ldg(np);     nxt[1] = __ldg(np + 1);
            nxt[2] = __ldg(np + 2); nxt[3] = __ldg(np + 3);
        }
        const uint32_t* bw = (const uint32_t*)cur;
#pragma unroll
        for (int mt = 0; mt < 4; mt++) {
            uint32_t ah[4];
            ldsm4(ah, sbA + (uint32_t)(M0 + mt * 16 + arow) * AROWB
                       + (uint32_t)ks * 32 + ak16off);
#pragma unroll
            for (int nt = 0; nt < 8; nt++)
                mma16816h(C[mt][nt], ah, bw[2 * nt], bw[2 * nt + 1]);
        }
    }
}

__global__ void __launch_bounds__(256, 2) nilut_mma(
    const float* __restrict__ rgb, const float* __restrict__ W0,
    const float* __restrict__ b1, const float* __restrict__ b2,
    const float* __restrict__ W3, const float* __restrict__ b3,
    float* __restrict__ out, int HW)
{
    extern __shared__ __align__(1024) char sm[];
    const uint32_t sb = s2u(sm);
    const int tid = threadIdx.x, wid = tid >> 5, lane = tid & 31;

    const int mg = wid & 1, ng = wid >> 1;
    const int M0 = mg * 64;
    const int arow = lane & 15, ak16off = ((lane >> 4) & 1) * 16;

    // per-warp fragment pointers (layer stride = 4*16*128 uint4 = 8192)
    const uint4* bp1 = (const uint4*)g_bfrag + (size_t)ng * 2048 + lane * 4;
    const uint4* bp2 = (const uint4*)g_bfrag + (size_t)(4 + ng) * 2048 + lane * 4;

    // kick off B prefetch for layer-1 ks=0 immediately
    uint4 bb[2][4];
    bb[0][0] = __ldg(bp1);     bb[0][1] = __ldg(bp1 + 1);
    bb[0][2] = __ldg(bp1 + 2); bb[0][3] = __ldg(bp1 + 3);

    const int pix0 = blockIdx.x * MTILE;
    const int b = pix0 / HW, hw0 = pix0 - b * HW;

    // stage small tensors
    float* b1s = (float*)(sm + OFF_B1);
    float* b2s = (float*)(sm + OFF_B2);
    float* w3s = (float*)(sm + OFF_W3);
    float* b3s = (float*)(sm + OFF_B3);
    float* w0s  = (float*)(sm + OFF_W0);
    float* cvec = (float*)(sm + OFF_CV);
    float* rgbs = (float*)(sm + OFF_RGB);

    b1s[tid] = b1[tid];
    b2s[tid] = b2[tid];
#pragma unroll
    for (int c = 0; c < 3; c++) w3s[c * 256 + tid] = W3[3 * tid + c];
    if (tid < 4) b3s[tid] = (tid < 3) ? b3[tid] : 0.f;
    for (int i = tid; i < 768; i += 256) w0s[i] = W0[i];
    cvec[tid] = g_cstyle[b * HID + tid];
    for (int i = tid; i < 384; i += 256) {
        int c = i >> 7, px = i & 127;
        rgbs[c * 128 + px] = rgb[(size_t)(b * 3 + c) * HW + hw0 + px];
    }
    __syncthreads();

    // ---- layer 0 prologue: A = fp16(gelu(rgb.W0[0:3] + cvec)) ----
    {
        int wq = wid & 3, half = wid >> 2;   // 4 pixel groups x 2 j-halves
        int p = wq * 32 + lane;              // 0..127
        float rr = rgbs[p], gg = rgbs[128 + p], uu = rgbs[256 + p];
        char* arow_p = sm + OFF_A + p * AROWB;
#pragma unroll 4
        for (int q = 0; q < 64; q++) {
            int j = half * 128 + 2 * q;
            float2 w0a = *(const float2*)&w0s[j];
            float2 w0b = *(const float2*)&w0s[256 + j];
            float2 w0c = *(const float2*)&w0s[512 + j];
            float2 cv  = *(const float2*)&cvec[j];
            float a0 = fmaf(rr, w0a.x, fmaf(gg, w0b.x, fmaf(uu, w0c.x, cv.x)));
            float a1 = fmaf(rr, w0a.y, fmaf(gg, w0b.y, fmaf(uu, w0c.y, cv.y)));
            *(uint32_t*)(arow_p + j * 2) = pack_h2(gelu_f(a0), gelu_f(a1));
        }
    }
    __syncthreads();   // A ready

    uint32_t C[4][8][2];
#pragma unroll
    for (int mt = 0; mt < 4; mt++)
#pragma unroll
        for (int nt = 0; nt < 8; nt++) { C[mt][nt][0] = 0u; C[mt][nt][1] = 0u; }

    // ---- layer 1 GEMM (tail-prefetches layer-2 ks=0) ----
    run_layer(sb + OFF_A, bp1, bp2, M0, arow, ak16off, C, bb);
    __syncthreads();   // all layer-1 A reads done before overwrite

    // ---- epilogue 1: C -> gelu -> A (fp16), zero C ----
    {
        const int r0b = M0 + (lane >> 2);
#pragma unroll
        for (int mt = 0; mt < 4; mt++) {
            int r0 = r0b + mt * 16, r1 = r0 + 8;
#pragma unroll
            for (int nt = 0; nt < 8; nt++) {
                int j0 = ng * 64 + nt * 8 + (lane & 3) * 2;
                float2 bj = *(const float2*)(sm + OFF_B1 + j0 * 4);
                float2 u0 = unpack_h2(C[mt][nt][0]);
                float2 u1 = unpack_h2(C[mt][nt][1]);
                float v0 = gelu_f(u0.x + bj.x);
                float v1 = gelu_f(u0.y + bj.y);
                float v2 = gelu_f(u1.x + bj.x);
                float v3 = gelu_f(u1.y + bj.y);
                *(uint32_t*)(sm + OFF_A + r0 * AROWB + j0 * 2) = pack_h2(v0, v1);
                *(uint32_t*)(sm + OFF_A + r1 * AROWB + j0 * 2) = pack_h2(v2, v3);
                C[mt][nt][0] = 0u; C[mt][nt][1] = 0u;
            }
        }
    }
    __syncthreads();   // A ready for layer 2

    // ---- layer 2 GEMM ----
    run_layer(sb + OFF_A, bp2, nullptr, M0, arow, ak16off, C, bb);

    // ---- head epilogue: gelu -> dot W3 -> reduce -> sigmoid ----
    {
        float* red = (float*)(sm + OFF_RED);   // [128][3][4]
        float acc[4][2][3];
#pragma unroll
        for (int mt = 0; mt < 4; mt++)
#pragma unroll
            for (int h = 0; h < 2; h++)
                acc[mt][h][0] = acc[mt][h][1] = acc[mt][h][2] = 0.f;

#pragma unroll
        for (int mt = 0; mt < 4; mt++) {
#pragma unroll
            for (int nt = 0; nt < 8; nt++) {
                int j0 = ng * 64 + nt * 8 + (lane & 3) * 2;
                float2 bj = *(const float2*)(sm + OFF_B2 + j0 * 4);
                float2 wx = *(const float2*)(sm + OFF_W3 + j0 * 4);
                float2 wy = *(const float2*)(sm + OFF_W3 + 1024 + j0 * 4);
                float2 wz = *(const float2*)(sm + OFF_W3 + 2048 + j0 * 4);
                float2 u0 = unpack_h2(C[mt][nt][0]);
                float2 u1 = unpack_h2(C[mt][nt][1]);
                float v0 = gelu_f(u0.x + bj.x);
                float v1 = gelu_f(u0.y + bj.y);
                float v2 = gelu_f(u1.x + bj.x);
                float v3 = gelu_f(u1.y + bj.y);
                acc[mt][0][0] = fmaf(v0, wx.x, fmaf(v1, wx.y, acc[mt][0][0]));
                acc[mt][0][1] = fmaf(v0, wy.x, fmaf(v1, wy.y, acc[mt][0][1]));
                acc[mt][0][2] = fmaf(v0, wz.x, fmaf(v1, wz.y, acc[mt][0][2]));
                acc[mt][1][0] = fmaf(v2, wx.x, fmaf(v3, wx.y, acc[mt][1][0]));
                acc[mt][1][1] = fmaf(v2, wy.x, fmaf(v3, wy.y, acc[mt][1][1]));
                acc[mt][1][2] = fmaf(v2, wz.x, fmaf(v3, wz.y, acc[mt][1][2]));
            }
        }
#pragma unroll
        for (int mt = 0; mt < 4; mt++)
#pragma unroll
            for (int h = 0; h < 2; h++)
#pragma unroll
                for (int ch = 0; ch < 3; ch++) {
                    float v = acc[mt][h][ch];
                    v += __shfl_xor_sync(0xffffffffu, v, 1);
                    v += __shfl_xor_sync(0xffffffffu, v, 2);
                    acc[mt][h][ch] = v;
                }
        if ((lane & 3) == 0) {
#pragma unroll
            for (int mt = 0; mt < 4; mt++)
#pragma unroll
                for (int h = 0; h < 2; h++) {
                    int r = M0 + mt * 16 + (lane >> 2) + h * 8;
#pragma unroll
                    for (int ch = 0; ch < 3; ch++)
                        red[(r * 3 + ch) * 4 + ng] = acc[mt][h][ch];
                }
        }
        __syncthreads();
        for (int i = tid; i < 384; i += 256) {
            int ch = i >> 7, row = i & 127;
            const float* rr = &red[(row * 3 + ch) * 4];
            float s = rr[0] + rr[1] + rr[2] + rr[3] + b3s[ch];
            out[(size_t)(b * 3 + ch) * HW + hw0 + row] = 1.f / (1.f + expf(-s));
        }
    }
}

extern "C" void kernel_launch(void* const* d_in, const int* in_sizes, int n_in,
                              void* d_out, int out_size) {
    const float* rgb  = (const float*)d_in[0];
    const int*   sidx = (const int*)  d_in[1];
    const float* emb  = (const float*)d_in[2];
    const float* W0   = (const float*)d_in[3];
    const float* b0   = (const float*)d_in[4];
    const float* W1   = (const float*)d_in[5];
    const float* b1   = (const float*)d_in[6];
    const float* W2   = (const float*)d_in[7];
    const float* b2   = (const float*)d_in[8];
    const float* W3   = (const float*)d_in[9];
    const float* b3   = (const float*)d_in[10];
    float* out = (float*)d_out;

    int B  = in_sizes[1];
    int HW = in_sizes[0] / (3 * B);
    int N  = B * HW;

    prep_all<<<256 + B, 256>>>(W1, W2, sidx, emb, W0, b0);

    cudaFuncSetAttribute(nilut_mma, cudaFuncAttributeMaxDynamicSharedMemorySize, SMEM_TOT);
    nilut_mma<<<N / MTILE, 256, SMEM_TOT>>>(rgb, W0, b1, b2, W3, b3, out, HW);
}

// round 11
// speedup vs baseline: 2.3831x; 2.3831x over previous
#include <cuda_runtime.h>
#include <cuda_fp16.h>
#include <cstdint>

#define HID 256
#define MTILE 128

#define AROWB 528
// ---- smem byte offsets (16B aligned) ----
#define OFF_A    0        // 128 * 528 = 67584
#define OFF_B1   67584    // 128 half2
#define OFF_B2   68096    // 128 half2
#define OFF_B3   68608    // 4 f32
#define OFF_W0   68624    // 768 f32
#define OFF_CV   71696    // 256 f32
#define OFF_RGB  72720    // 384 f32
#define SMEM_TOT 74256

// B in mma-fragment order (same mapping as R9):
// index = ((((l*4 + wn)*16 + ks)*32 + lane)*16 + r)
__device__ __align__(16) uint32_t g_bfrag[65536];
// W3 head fragments: [ks16][lane32] x 2 regs (cols 3..7 zero)
__device__ __align__(16) uint2 g_w3f[512];
__device__ float g_cstyle[16 * HID];

// ---------- helpers ----------
__device__ __forceinline__ uint32_t s2u(const void* p) {
    uint32_t a;
    asm("{ .reg .u64 t; cvta.to.shared.u64 t, %1; cvt.u32.u64 %0, t; }" : "=r"(a) : "l"(p));
    return a;
}
__device__ __forceinline__ void ldsm4(uint32_t* r, uint32_t addr) {
    asm volatile("ldmatrix.sync.aligned.m8n8.x4.shared.b16 {%0,%1,%2,%3}, [%4];"
                 : "=r"(r[0]), "=r"(r[1]), "=r"(r[2]), "=r"(r[3]) : "r"(addr));
}
__device__ __forceinline__ void mma16816h(uint32_t* d, const uint32_t* a, uint32_t b0, uint32_t b1) {
    asm volatile("mma.sync.aligned.m16n8k16.row.col.f16.f16.f16.f16 "
                 "{%0,%1}, {%2,%3,%4,%5}, {%6,%7}, {%0,%1};"
                 : "+r"(d[0]), "+r"(d[1])
                 : "r"(a[0]), "r"(a[1]), "r"(a[2]), "r"(a[3]), "r"(b0), "r"(b1));
}
__device__ __forceinline__ void mma16816f(float* d, const uint32_t* a, uint32_t b0, uint32_t b1) {
    asm volatile("mma.sync.aligned.m16n8k16.row.col.f32.f16.f16.f32 "
                 "{%0,%1,%2,%3}, {%4,%5,%6,%7}, {%8,%9}, {%0,%1,%2,%3};"
                 : "+f"(d[0]), "+f"(d[1]), "+f"(d[2]), "+f"(d[3])
                 : "r"(a[0]), "r"(a[1]), "r"(a[2]), "r"(a[3]), "r"(b0), "r"(b1));
}
__device__ __forceinline__ uint32_t pack_h2(float lo, float hi) {
    __half2 h = __floats2half2_rn(lo, hi);
    return *(uint32_t*)&h;
}
// tanh-form gelu on a packed half2 (5 instr / 2 values)
__device__ __forceinline__ uint32_t gelu_h2(uint32_t xu) {
    const __half2 C0 = __float2half2_rn(0.7978845608f);
    const __half2 C1 = __float2half2_rn(0.0356774081f);
    const __half2 H5 = __float2half2_rn(0.5f);
    __half2 x = *(__half2*)&xu;
    __half2 x2 = __hmul2(x, x);
    __half2 y = __hmul2(x, __hfma2(x2, C1, C0));
    uint32_t yu = *(uint32_t*)&y, tu;
    asm("tanh.approx.f16x2 %0, %1;" : "=r"(tu) : "r"(yu));
    __half2 t = *(__half2*)&tu;
    __half2 o = __hmul2(x, __hfma2(t, H5, H5));
    return *(uint32_t*)&o;
}
// exact erf-gelu for the (fp32) layer-0 prologue is replaced by same tanh form
// packed after fp32 matmul — consistency with hidden layers.

// ---------- merged pre-kernel ----------
__global__ void prep_all(const float* __restrict__ W1, const float* __restrict__ W2,
                         const int* __restrict__ sidx, const float* __restrict__ emb,
                         const float* __restrict__ W0, const float* __restrict__ b0,
                         const float* __restrict__ W3, int B) {
    if (blockIdx.x < 256) {
        int idx = blockIdx.x * 256 + threadIdx.x;     // 0..65535
        int r    = idx & 15;
        int lane = (idx >> 4) & 31;
        int ks   = (idx >> 9) & 15;
        int wn   = (idx >> 13) & 3;
        int l    = (idx >> 15) & 1;
        int n = wn * 64 + (r >> 1) * 8 + (lane >> 2);
        int k = ks * 16 + (r & 1) * 8 + (lane & 3) * 2;
        const float* Wm = l ? W2 : W1;
        g_bfrag[idx] = pack_h2(Wm[k * HID + n], Wm[(k + 1) * HID + n]);
    } else if ((int)blockIdx.x < 256 + B) {
        int b = blockIdx.x - 256, j = threadIdx.x;
        int s = sidx[b];
        float acc = b0[j];
#pragma unroll 8
        for (int k = 0; k < 64; k++)
            acc = fmaf(emb[s * 64 + k], W0[(3 + k) * HID + j], acc);
        g_cstyle[b * HID + j] = acc;
    } else {
        // W3 head fragments
        for (int e = threadIdx.x; e < 512; e += 256) {
            int ks = e >> 5, lane = e & 31;
            int n = lane >> 2;
            int k0 = ks * 16 + (lane & 3) * 2;
            float v00 = (n < 3) ? W3[k0 * 3 + n] : 0.f;
            float v01 = (n < 3) ? W3[(k0 + 1) * 3 + n] : 0.f;
            float v10 = (n < 3) ? W3[(k0 + 8) * 3 + n] : 0.f;
            float v11 = (n < 3) ? W3[(k0 + 9) * 3 + n] : 0.f;
            g_w3f[e] = make_uint2(pack_h2(v00, v01), pack_h2(v10, v11));
        }
    }
}

// ---------- main kernel ----------
__device__ __forceinline__ void run_layer(uint32_t sbA, const uint4* bp, const uint4* bpn,
                                          int M0, int arow, int ak16off,
                                          uint32_t C[4][8][2], uint4 bb[2][4]) {
#pragma unroll
    for (int ks = 0; ks < 16; ks++) {
        uint4* cur = bb[ks & 1];
        uint4* nxt = bb[(ks + 1) & 1];
        const uint4* np = (ks < 15) ? bp + (ks + 1) * 128 : bpn;
        if (np) {
            nxt[0] = __ldg(np);     nxt[1] = __ldg(np + 1);
            nxt[2] = __ldg(np + 2); nxt[3] = __ldg(np + 3);
        }
        const uint32_t* bw = (const uint32_t*)cur;
#pragma unroll
        for (int mt = 0; mt < 4; mt++) {
            uint32_t ah[4];
            ldsm4(ah, sbA + (uint32_t)(M0 + mt * 16 + arow) * AROWB
                       + (uint32_t)ks * 32 + ak16off);
#pragma unroll
            for (int nt = 0; nt < 8; nt++)
                mma16816h(C[mt][nt], ah, bw[2 * nt], bw[2 * nt + 1]);
        }
    }
}

// epilogue: C(half2) + bias -> gelu -> A ; zero C
__device__ __forceinline__ void epi_gelu(char* sm, uint32_t C[4][8][2],
                                         int offB, int M0, int ng, int lane) {
    const uint32_t* bh = (const uint32_t*)(sm + offB) + ng * 32 + (lane & 3);
    const int r0b = M0 + (lane >> 2);
#pragma unroll
    for (int nt = 0; nt < 8; nt++) {
        uint32_t bju = bh[nt * 4];
        __half2 bj = *(__half2*)&bju;
        int j0 = ng * 64 + nt * 8 + (lane & 3) * 2;
#pragma unroll
        for (int mt = 0; mt < 4; mt++) {
            int r0 = r0b + mt * 16, r1 = r0 + 8;
            __half2 c0 = *(__half2*)&C[mt][nt][0];
            __half2 c1 = *(__half2*)&C[mt][nt][1];
            __half2 s0 = __hadd2(c0, bj);
            __half2 s1 = __hadd2(c1, bj);
            *(uint32_t*)(sm + OFF_A + r0 * AROWB + j0 * 2) = gelu_h2(*(uint32_t*)&s0);
            *(uint32_t*)(sm + OFF_A + r1 * AROWB + j0 * 2) = gelu_h2(*(uint32_t*)&s1);
            C[mt][nt][0] = 0u; C[mt][nt][1] = 0u;
        }
    }
}

__global__ void __launch_bounds__(256, 2) nilut_mma(
    const float* __restrict__ rgb, const float* __restrict__ W0,
    const float* __restrict__ b1, const float* __restrict__ b2,
    const float* __restrict__ b3,
    float* __restrict__ out, int HW)
{
    extern __shared__ __align__(1024) char sm[];
    const uint32_t sb = s2u(sm);
    const int tid = threadIdx.x, wid = tid >> 5, lane = tid & 31;

    const int mg = wid & 1, ng = wid >> 1;
    const int M0 = mg * 64;
    const int arow = lane & 15, ak16off = ((lane >> 4) & 1) * 16;

    const uint4* bp1 = (const uint4*)g_bfrag + (size_t)ng * 2048 + lane * 4;
    const uint4* bp2 = (const uint4*)g_bfrag + (size_t)(4 + ng) * 2048 + lane * 4;

    uint4 bb[2][4];
    bb[0][0] = __ldg(bp1);     bb[0][1] = __ldg(bp1 + 1);
    bb[0][2] = __ldg(bp1 + 2); bb[0][3] = __ldg(bp1 + 3);

    const int pix0 = blockIdx.x * MTILE;
    const int b = pix0 / HW, hw0 = pix0 - b * HW;

    float* b3s = (float*)(sm + OFF_B3);
    float* w0s  = (float*)(sm + OFF_W0);
    float* cvec = (float*)(sm + OFF_CV);
    float* rgbs = (float*)(sm + OFF_RGB);

    if (tid < 128) {
        ((uint32_t*)(sm + OFF_B1))[tid] = pack_h2(b1[2 * tid], b1[2 * tid + 1]);
        ((uint32_t*)(sm + OFF_B2))[tid] = pack_h2(b2[2 * tid], b2[2 * tid + 1]);
    }
    if (tid < 4) b3s[tid] = (tid < 3) ? b3[tid] : 0.f;
    for (int i = tid; i < 768; i += 256) w0s[i] = W0[i];
    cvec[tid] = g_cstyle[b * HID + tid];
    for (int i = tid; i < 384; i += 256) {
        int c = i >> 7, px = i & 127;
        rgbs[c * 128 + px] = rgb[(size_t)(b * 3 + c) * HW + hw0 + px];
    }
    __syncthreads();

    // ---- layer 0 prologue ----
    {
        int wq = wid & 3, half = wid >> 2;
        int p = wq * 32 + lane;
        float rr = rgbs[p], gg = rgbs[128 + p], uu = rgbs[256 + p];
        char* arow_p = sm + OFF_A + p * AROWB;
#pragma unroll 4
        for (int q = 0; q < 32; q++) {
            int j = half * 128 + 4 * q;
            float4 wa = *(const float4*)&w0s[j];
            float4 wb = *(const float4*)&w0s[256 + j];
            float4 wc = *(const float4*)&w0s[512 + j];
            float4 cv = *(const float4*)&cvec[j];
            float a0 = fmaf(rr, wa.x, fmaf(gg, wb.x, fmaf(uu, wc.x, cv.x)));
            float a1 = fmaf(rr, wa.y, fmaf(gg, wb.y, fmaf(uu, wc.y, cv.y)));
            float a2 = fmaf(rr, wa.z, fmaf(gg, wb.z, fmaf(uu, wc.z, cv.z)));
            float a3 = fmaf(rr, wa.w, fmaf(gg, wb.w, fmaf(uu, wc.w, cv.w)));
            uint2 st;
            st.x = gelu_h2(pack_h2(a0, a1));
            st.y = gelu_h2(pack_h2(a2, a3));
            *(uint2*)(arow_p + j * 2) = st;
        }
    }
    __syncthreads();

    uint32_t C[4][8][2];
#pragma unroll
    for (int mt = 0; mt < 4; mt++)
#pragma unroll
        for (int nt = 0; nt < 8; nt++) { C[mt][nt][0] = 0u; C[mt][nt][1] = 0u; }

    // ---- layer 1 ----
    run_layer(sb + OFF_A, bp1, bp2, M0, arow, ak16off, C, bb);
    __syncthreads();
    epi_gelu(sm, C, OFF_B1, M0, ng, lane);
    __syncthreads();

    // ---- layer 2 ----
    run_layer(sb + OFF_A, bp2, nullptr, M0, arow, ak16off, C, bb);
    __syncthreads();
    epi_gelu(sm, C, OFF_B2, M0, ng, lane);
    __syncthreads();

    // ---- head: A x W3frag (f32 accum), sigmoid, store ----
    {
        const int rbase = wid * 16;
        float Ch[4] = {0.f, 0.f, 0.f, 0.f};
        const uint2* wf = g_w3f + lane;
#pragma unroll
        for (int ks = 0; ks < 16; ks++) {
            uint2 bf = __ldg(wf + ks * 32);
            uint32_t ah[4];
            ldsm4(ah, sb + OFF_A + (uint32_t)(rbase + arow) * AROWB
                       + (uint32_t)ks * 32 + ak16off);
            mma16816f(Ch, ah, bf.x, bf.y);
        }
        int c0 = (lane & 3) * 2;
        int r0 = rbase + (lane >> 2);
        if (c0 < 3) {
            float s0 = Ch[0] + b3s[c0];
            float s2 = Ch[2] + b3s[c0];
            out[(size_t)(b * 3 + c0) * HW + hw0 + r0]     = 1.f / (1.f + expf(-s0));
            out[(size_t)(b * 3 + c0) * HW + hw0 + r0 + 8] = 1.f / (1.f + expf(-s2));
        }
        if (c0 + 1 < 3) {
            float s1 = Ch[1] + b3s[c0 + 1];
            float s3 = Ch[3] + b3s[c0 + 1];
            out[(size_t)(b * 3 + c0 + 1) * HW + hw0 + r0]     = 1.f / (1.f + expf(-s1));
            out[(size_t)(b * 3 + c0 + 1) * HW + hw0 + r0 + 8] = 1.f / (1.f + expf(-s3));
        }
    }
}

extern "C" void kernel_launch(void* const* d_in, const int* in_sizes, int n_in,
                              void* d_out, int out_size) {
    const float* rgb  = (const float*)d_in[0];
    const int*   sidx = (const int*)  d_in[1];
    const float* emb  = (const float*)d_in[2];
    const float* W0   = (const float*)d_in[3];
    const float* b0   = (const float*)d_in[4];
    const float* W1   = (const float*)d_in[5];
    const float* b1   = (const float*)d_in[6];
    const float* W2   = (const float*)d_in[7];
    const float* b2   = (const float*)d_in[8];
    const float* W3   = (const float*)d_in[9];
    const float* b3   = (const float*)d_in[10];
    float* out = (float*)d_out;

    int B  = in_sizes[1];
    int HW = in_sizes[0] / (3 * B);
    int N  = B * HW;

    prep_all<<<257 + B, 256>>>(W1, W2, sidx, emb, W0, b0, W3, B);

    cudaFuncSetAttribute(nilut_mma, cudaFuncAttributeMaxDynamicSharedMemorySize, SMEM_TOT);
    nilut_mma<<<N / MTILE, 256, SMEM_TOT>>>(rgb, W0, b1, b2, b3, out, HW);
}

// round 12
// speedup vs baseline: 2.3882x; 1.0021x over previous
#include <cuda_runtime.h>
#include <cuda_fp16.h>
#include <cstdint>

#define HID 256
#define MTILE 128

#define AROWB 528
// ---- smem byte offsets (16B aligned) ----
#define OFF_A    0        // 128 * 528 = 67584
#define OFF_B1   67584    // 128 half2
#define OFF_B2   68096    // 128 half2
#define OFF_B3   68608    // 4 f32
#define OFF_W0   68624    // 768 f32
#define OFF_CV   71696    // 256 f32
#define OFF_RGB  72720    // 384 f32
#define SMEM_TOT 74256

// B in mma-fragment order:
// index = ((((l*4 + wn)*16 + ks)*32 + lane)*16 + r)
__device__ __align__(16) uint32_t g_bfrag[65536];
// W3 head fragments: [ks16][lane32] x 2 regs (cols 3..7 zero)
__device__ __align__(16) uint2 g_w3f[512];
__device__ float g_cstyle[16 * HID];

// ---------- helpers ----------
__device__ __forceinline__ uint32_t s2u(const void* p) {
    uint32_t a;
    asm("{ .reg .u64 t; cvta.to.shared.u64 t, %1; cvt.u32.u64 %0, t; }" : "=r"(a) : "l"(p));
    return a;
}
__device__ __forceinline__ void ldsm4(uint32_t* r, uint32_t addr) {
    asm volatile("ldmatrix.sync.aligned.m8n8.x4.shared.b16 {%0,%1,%2,%3}, [%4];"
                 : "=r"(r[0]), "=r"(r[1]), "=r"(r[2]), "=r"(r[3]) : "r"(addr));
}
__device__ __forceinline__ uint4 ldcg(const uint4* p) {
    uint4 v;
    asm("ld.global.cg.v4.u32 {%0,%1,%2,%3}, [%4];"
        : "=r"(v.x), "=r"(v.y), "=r"(v.z), "=r"(v.w) : "l"(p));
    return v;
}
__device__ __forceinline__ void mma16816h(uint32_t* d, const uint32_t* a, uint32_t b0, uint32_t b1) {
    asm volatile("mma.sync.aligned.m16n8k16.row.col.f16.f16.f16.f16 "
                 "{%0,%1}, {%2,%3,%4,%5}, {%6,%7}, {%0,%1};"
                 : "+r"(d[0]), "+r"(d[1])
                 : "r"(a[0]), "r"(a[1]), "r"(a[2]), "r"(a[3]), "r"(b0), "r"(b1));
}
__device__ __forceinline__ void mma16816f(float* d, const uint32_t* a, uint32_t b0, uint32_t b1) {
    asm volatile("mma.sync.aligned.m16n8k16.row.col.f32.f16.f16.f32 "
                 "{%0,%1,%2,%3}, {%4,%5,%6,%7}, {%8,%9}, {%0,%1,%2,%3};"
                 : "+f"(d[0]), "+f"(d[1]), "+f"(d[2]), "+f"(d[3])
                 : "r"(a[0]), "r"(a[1]), "r"(a[2]), "r"(a[3]), "r"(b0), "r"(b1));
}
__device__ __forceinline__ uint32_t pack_h2(float lo, float hi) {
    __half2 h = __floats2half2_rn(lo, hi);
    return *(uint32_t*)&h;
}
// tanh-form gelu on a packed half2
__device__ __forceinline__ uint32_t gelu_h2(uint32_t xu) {
    const __half2 C0 = __float2half2_rn(0.7978845608f);
    const __half2 C1 = __float2half2_rn(0.0356774081f);
    const __half2 H5 = __float2half2_rn(0.5f);
    __half2 x = *(__half2*)&xu;
    __half2 x2 = __hmul2(x, x);
    __half2 y = __hmul2(x, __hfma2(x2, C1, C0));
    uint32_t yu = *(uint32_t*)&y, tu;
    asm("tanh.approx.f16x2 %0, %1;" : "=r"(tu) : "r"(yu));
    __half2 t = *(__half2*)&tu;
    __half2 o = __hmul2(x, __hfma2(t, H5, H5));
    return *(uint32_t*)&o;
}

// ---------- merged pre-kernel ----------
__global__ void prep_all(const float* __restrict__ W1, const float* __restrict__ W2,
                         const int* __restrict__ sidx, const float* __restrict__ emb,
                         const float* __restrict__ W0, const float* __restrict__ b0,
                         const float* __restrict__ W3, int B) {
    if (blockIdx.x < 256) {
        int idx = blockIdx.x * 256 + threadIdx.x;
        int r    = idx & 15;
        int lane = (idx >> 4) & 31;
        int ks   = (idx >> 9) & 15;
        int wn   = (idx >> 13) & 3;
        int l    = (idx >> 15) & 1;
        int n = wn * 64 + (r >> 1) * 8 + (lane >> 2);
        int k = ks * 16 + (r & 1) * 8 + (lane & 3) * 2;
        const float* Wm = l ? W2 : W1;
        g_bfrag[idx] = pack_h2(Wm[k * HID + n], Wm[(k + 1) * HID + n]);
    } else if ((int)blockIdx.x < 256 + B) {
        int b = blockIdx.x - 256, j = threadIdx.x;
        int s = sidx[b];
        float acc = b0[j];
#pragma unroll 8
        for (int k = 0; k < 64; k++)
            acc = fmaf(emb[s * 64 + k], W0[(3 + k) * HID + j], acc);
        g_cstyle[b * HID + j] = acc;
    } else {
        for (int e = threadIdx.x; e < 512; e += 256) {
            int ks = e >> 5, lane = e & 31;
            int n = lane >> 2;
            int k0 = ks * 16 + (lane & 3) * 2;
            float v00 = (n < 3) ? W3[k0 * 3 + n] : 0.f;
            float v01 = (n < 3) ? W3[(k0 + 1) * 3 + n] : 0.f;
            float v10 = (n < 3) ? W3[(k0 + 8) * 3 + n] : 0.f;
            float v11 = (n < 3) ? W3[(k0 + 9) * 3 + n] : 0.f;
            g_w3f[e] = make_uint2(pack_h2(v00, v01), pack_h2(v10, v11));
        }
    }
}

// ---------- main kernel ----------
// Software-pipelined layer: A fragments prefetched one (mt,ks)-step ahead,
// B double-buffered across ks via L1-bypassing LDG.
__device__ __forceinline__ void run_layer(uint32_t sbA, const uint4* bp, const uint4* bpn,
                                          int M0, int arow, int ak16off,
                                          uint32_t C[4][8][2], uint4 bb[2][4]) {
    const uint32_t abase = sbA + (uint32_t)(M0 + arow) * AROWB + ak16off;
    uint32_t ahA[4], ahB[4];
    ldsm4(ahA, abase);                 // (ks=0, mt=0)
#pragma unroll
    for (int ks = 0; ks < 16; ks++) {
        uint4* nxt = bb[(ks + 1) & 1];
        const uint4* np = (ks < 15) ? bp + (ks + 1) * 128 : bpn;
        if (np) {
            nxt[0] = ldcg(np);     nxt[1] = ldcg(np + 1);
            nxt[2] = ldcg(np + 2); nxt[3] = ldcg(np + 3);
        }
        const uint32_t* bw = (const uint32_t*)bb[ks & 1];
#pragma unroll
        for (int mt = 0; mt < 4; mt++) {
            // prefetch next A fragment (one step ahead)
            const int nmt = (mt + 1) & 3;
            const int nks = (mt == 3) ? ks + 1 : ks;
            if (nks < 16)
                ldsm4(ahB, abase + (uint32_t)nmt * (16 * AROWB) + (uint32_t)nks * 32);
#pragma unroll
            for (int nt = 0; nt < 8; nt++)
                mma16816h(C[mt][nt], ahA, bw[2 * nt], bw[2 * nt + 1]);
#pragma unroll
            for (int q = 0; q < 4; q++) { uint32_t t = ahA[q]; ahA[q] = ahB[q]; ahB[q] = t; }
        }
    }
}

// epilogue: C(half2) + bias -> gelu -> A ; zero C
__device__ __forceinline__ void epi_gelu(char* sm, uint32_t C[4][8][2],
                                         int offB, int M0, int ng, int lane) {
    const uint32_t* bh = (const uint32_t*)(sm + offB) + ng * 32 + (lane & 3);
    const int r0b = M0 + (lane >> 2);
#pragma unroll
    for (int nt = 0; nt < 8; nt++) {
        uint32_t bju = bh[nt * 4];
        __half2 bj = *(__half2*)&bju;
        int j0 = ng * 64 + nt * 8 + (lane & 3) * 2;
#pragma unroll
        for (int mt = 0; mt < 4; mt++) {
            int r0 = r0b + mt * 16, r1 = r0 + 8;
            __half2 c0 = *(__half2*)&C[mt][nt][0];
            __half2 c1 = *(__half2*)&C[mt][nt][1];
            __half2 s0 = __hadd2(c0, bj);
            __half2 s1 = __hadd2(c1, bj);
            *(uint32_t*)(sm + OFF_A + r0 * AROWB + j0 * 2) = gelu_h2(*(uint32_t*)&s0);
            *(uint32_t*)(sm + OFF_A + r1 * AROWB + j0 * 2) = gelu_h2(*(uint32_t*)&s1);
            C[mt][nt][0] = 0u; C[mt][nt][1] = 0u;
        }
    }
}

__global__ void __launch_bounds__(256, 2) nilut_mma(
    const float* __restrict__ rgb, const float* __restrict__ W0,
    const float* __restrict__ b1, const float* __restrict__ b2,
    const float* __restrict__ b3,
    float* __restrict__ out, int HW)
{
    extern __shared__ __align__(1024) char sm[];
    const uint32_t sb = s2u(sm);
    const int tid = threadIdx.x, wid = tid >> 5, lane = tid & 31;

    const int mg = wid & 1, ng = wid >> 1;
    const int M0 = mg * 64;
    const int arow = lane & 15, ak16off = ((lane >> 4) & 1) * 16;

    const uint4* bp1 = (const uint4*)g_bfrag + (size_t)ng * 2048 + lane * 4;
    const uint4* bp2 = (const uint4*)g_bfrag + (size_t)(4 + ng) * 2048 + lane * 4;

    uint4 bb[2][4];
    bb[0][0] = ldcg(bp1);     bb[0][1] = ldcg(bp1 + 1);
    bb[0][2] = ldcg(bp1 + 2); bb[0][3] = ldcg(bp1 + 3);

    const int pix0 = blockIdx.x * MTILE;
    const int b = pix0 / HW, hw0 = pix0 - b * HW;

    float* b3s = (float*)(sm + OFF_B3);
    float* w0s  = (float*)(sm + OFF_W0);
    float* cvec = (float*)(sm + OFF_CV);
    float* rgbs = (float*)(sm + OFF_RGB);

    if (tid < 128) {
        ((uint32_t*)(sm + OFF_B1))[tid] = pack_h2(b1[2 * tid], b1[2 * tid + 1]);
        ((uint32_t*)(sm + OFF_B2))[tid] = pack_h2(b2[2 * tid], b2[2 * tid + 1]);
    }
    if (tid < 4) b3s[tid] = (tid < 3) ? b3[tid] : 0.f;
    for (int i = tid; i < 768; i += 256) w0s[i] = W0[i];
    cvec[tid] = g_cstyle[b * HID + tid];
    for (int i = tid; i < 384; i += 256) {
        int c = i >> 7, px = i & 127;
        rgbs[c * 128 + px] = rgb[(size_t)(b * 3 + c) * HW + hw0 + px];
    }
    __syncthreads();

    // ---- layer 0 prologue ----
    {
        int wq = wid & 3, half = wid >> 2;
        int p = wq * 32 + lane;
        float rr = rgbs[p], gg = rgbs[128 + p], uu = rgbs[256 + p];
        char* arow_p = sm + OFF_A + p * AROWB;
#pragma unroll 4
        for (int q = 0; q < 32; q++) {
            int j = half * 128 + 4 * q;
            float4 wa = *(const float4*)&w0s[j];
            float4 wb = *(const float4*)&w0s[256 + j];
            float4 wc = *(const float4*)&w0s[512 + j];
            float4 cv = *(const float4*)&cvec[j];
            float a0 = fmaf(rr, wa.x, fmaf(gg, wb.x, fmaf(uu, wc.x, cv.x)));
            float a1 = fmaf(rr, wa.y, fmaf(gg, wb.y, fmaf(uu, wc.y, cv.y)));
            float a2 = fmaf(rr, wa.z, fmaf(gg, wb.z, fmaf(uu, wc.z, cv.z)));
            float a3 = fmaf(rr, wa.w, fmaf(gg, wb.w, fmaf(uu, wc.w, cv.w)));
            uint2 st;
            st.x = gelu_h2(pack_h2(a0, a1));
            st.y = gelu_h2(pack_h2(a2, a3));
            *(uint2*)(arow_p + j * 2) = st;
        }
    }
    __syncthreads();

    uint32_t C[4][8][2];
#pragma unroll
    for (int mt = 0; mt < 4; mt++)
#pragma unroll
        for (int nt = 0; nt < 8; nt++) { C[mt][nt][0] = 0u; C[mt][nt][1] = 0u; }

    // ---- layer 1 ----
    run_layer(sb + OFF_A, bp1, bp2, M0, arow, ak16off, C, bb);
    __syncthreads();
    epi_gelu(sm, C, OFF_B1, M0, ng, lane);
    __syncthreads();

    // ---- layer 2 ----
    run_layer(sb + OFF_A, bp2, nullptr, M0, arow, ak16off, C, bb);
    __syncthreads();
    epi_gelu(sm, C, OFF_B2, M0, ng, lane);
    __syncthreads();

    // ---- head: A x W3frag (f32 accum), sigmoid, store ----
    {
        const int rbase = wid * 16;
        float Ch[4] = {0.f, 0.f, 0.f, 0.f};
        const uint2* wf = g_w3f + lane;
#pragma unroll
        for (int ks = 0; ks < 16; ks++) {
            uint2 bf = __ldg(wf + ks * 32);
            uint32_t ah[4];
            ldsm4(ah, sb + OFF_A + (uint32_t)(rbase + arow) * AROWB
                       + (uint32_t)ks * 32 + ak16off);
            mma16816f(Ch, ah, bf.x, bf.y);
        }
        int c0 = (lane & 3) * 2;
        int r0 = rbase + (lane >> 2);
        if (c0 < 3) {
            float s0 = Ch[0] + b3s[c0];
            float s2 = Ch[2] + b3s[c0];
            out[(size_t)(b * 3 + c0) * HW + hw0 + r0]     = 1.f / (1.f + expf(-s0));
            out[(size_t)(b * 3 + c0) * HW + hw0 + r0 + 8] = 1.f / (1.f + expf(-s2));
        }
        if (c0 + 1 < 3) {
            float s1 = Ch[1] + b3s[c0 + 1];
            float s3 = Ch[3] + b3s[c0 + 1];
            out[(size_t)(b * 3 + c0 + 1) * HW + hw0 + r0]     = 1.f / (1.f + expf(-s1));
            out[(size_t)(b * 3 + c0 + 1) * HW + hw0 + r0 + 8] = 1.f / (1.f + expf(-s3));
        }
    }
}

extern "C" void kernel_launch(void* const* d_in, const int* in_sizes, int n_in,
                              void* d_out, int out_size) {
    const float* rgb  = (const float*)d_in[0];
    const int*   sidx = (const int*)  d_in[1];
    const float* emb  = (const float*)d_in[2];
    const float* W0   = (const float*)d_in[3];
    const float* b0   = (const float*)d_in[4];
    const float* W1   = (const float*)d_in[5];
    const float* b1   = (const float*)d_in[6];
    const float* W2   = (const float*)d_in[7];
    const float* b2   = (const float*)d_in[8];
    const float* W3   = (const float*)d_in[9];
    const float* b3   = (const float*)d_in[10];
    float* out = (float*)d_out;

    int B  = in_sizes[1];
    int HW = in_sizes[0] / (3 * B);
    int N  = B * HW;

    prep_all<<<257 + B, 256>>>(W1, W2, sidx, emb, W0, b0, W3, B);

    cudaFuncSetAttribute(nilut_mma, cudaFuncAttributeMaxDynamicSharedMemorySize, SMEM_TOT);
    nilut_mma<<<N / MTILE, 256, SMEM_TOT>>>(rgb, W0, b1, b2, b3, out, HW);
}